// round 1
// baseline (speedup 1.0000x reference)
#include <cuda_runtime.h>
#include <math_constants.h>

#define N_SPIKES 16384
#define N_UNITS  256
#define N_NEIGHB 128
#define RANK     5
#define NCH      64
#define NCO      12
#define N_CAND   10
#define DDIM     60
#define OUT_COLS 61
#define CAP      2048

// Precomputed tables (device globals; no runtime allocation)
__device__ __align__(16) float g_H[N_NEIGHB * N_UNITS * DDIM];  // H[nid,u,:] = Coo_inv[nid] @ nu(nid,u)
__device__ float g_LLC[N_NEIGHB * N_UNITS];                     // logprop[u] - 0.5 * nu^T C nu
__device__ int   g_cursor[N_UNITS];
__device__ int   g_sn[N_UNITS * CAP];
__device__ float g_sq[N_UNITS * CAP];

// ---------------------------------------------------------------------------
// Kernel 1: per-neighborhood precompute of H and LLC. One block per nid.
// C held in shared with pitch 61 (conflict-free column access: gcd(29,32)=1).
// Each warp handles 32 units in batches of 8 (register tile: 2 d-rows x 8 units).
// Also zeroes the bucket cursors (block 0).
// ---------------------------------------------------------------------------
__global__ void __launch_bounds__(256) k_pre(const float* __restrict__ mu,
                                             const float* __restrict__ Cinv,
                                             const int*   __restrict__ obs_ix,
                                             const float* __restrict__ logprop)
{
    __shared__ float Csh[DDIM * 61];
    __shared__ float nub[8][8][64];   // [warp][unit-in-batch][e]
    __shared__ int   obs[NCO];

    const int nidv = blockIdx.x;
    const int t    = threadIdx.x;
    const int warp = t >> 5;
    const int lane = t & 31;

    if (nidv == 0) g_cursor[t] = 0;   // blockDim.x == 256 == N_UNITS

    if (t < NCO) obs[t] = obs_ix[nidv * NCO + t];

    const float* C = Cinv + nidv * (DDIM * DDIM);
    for (int i = t; i < DDIM * DDIM; i += 256) {
        int r = i / DDIM, c = i % DDIM;
        Csh[r * 61 + c] = C[i];
    }
    __syncthreads();

    const int d0 = lane;            // always valid (< 60)
    const int d1 = lane + 32;       // valid when lane < 28
    const bool has1 = (d1 < DDIM);
    const int r0 = d0 / NCO, k0 = d0 % NCO;
    const int r1 = has1 ? (d1 / NCO) : 0;
    const int k1 = has1 ? (d1 % NCO) : 0;
    const int o0 = obs[k0];
    const int o1 = obs[k1];

    for (int b = 0; b < 4; b++) {
        const int ubase = warp * 32 + b * 8;

        // gather nu for 8 units into shared
        #pragma unroll
        for (int j = 0; j < 8; j++) {
            const int u = ubase + j;
            nub[warp][j][d0] = mu[u * (RANK * NCH) + r0 * NCH + o0];
            if (has1)
                nub[warp][j][d1] = mu[u * (RANK * NCH) + r1 * NCH + o1];
        }
        __syncwarp();

        float acc0[8], acc1[8];
        #pragma unroll
        for (int j = 0; j < 8; j++) { acc0[j] = 0.f; acc1[j] = 0.f; }

        #pragma unroll 6
        for (int e = 0; e < DDIM; e++) {
            const float c0 = Csh[d0 * 61 + e];
            const float c1 = has1 ? Csh[d1 * 61 + e] : 0.f;
            #pragma unroll
            for (int j = 0; j < 8; j++) {
                const float ne = nub[warp][j][e];
                acc0[j] = fmaf(c0, ne, acc0[j]);
                acc1[j] = fmaf(c1, ne, acc1[j]);
            }
        }

        #pragma unroll
        for (int j = 0; j < 8; j++) {
            const int u = ubase + j;
            float* Hrow = g_H + (size_t)(nidv * N_UNITS + u) * DDIM;
            Hrow[d0] = acc0[j];
            if (has1) Hrow[d1] = acc1[j];
            // G = nu^T C nu = h . nu
            float part = acc0[j] * nub[warp][j][d0]
                       + (has1 ? acc1[j] * nub[warp][j][d1] : 0.f);
            #pragma unroll
            for (int o = 16; o; o >>= 1) part += __shfl_xor_sync(0xffffffffu, part, o);
            if (lane == 0)
                g_LLC[nidv * N_UNITS + u] = logprop[u] - 0.5f * part;
        }
        __syncwarp();
    }
}

// ---------------------------------------------------------------------------
// Kernel 2: per-spike responsibilities. One warp per spike.
// ll'_c = LLC[nid,u_c] + dot(xf, H[nid,u_c]);  ll'_noise = noise_log_prop.
// (base + m_ff terms cancel in the softmax.)
// Scatter (spike, q) records into per-unit buckets.
// ---------------------------------------------------------------------------
__global__ void __launch_bounds__(256) k_main(const float* __restrict__ features,
                                              const int*   __restrict__ cands,
                                              const int*   __restrict__ nid,
                                              const float* __restrict__ noise_lp)
{
    const int t    = threadIdx.x;
    const int warp = t >> 5;
    const int lane = t & 31;
    const int s    = blockIdx.x * 8 + warp;

    const float* xf = features + (size_t)s * DDIM;
    const float x0 = xf[lane];
    const float x1 = (lane < 28) ? xf[lane + 32] : 0.f;

    const int nidv  = nid[s];
    const int pbase = nidv * N_UNITS;
    const int ucached = (lane < N_CAND) ? cands[s * N_CAND + lane] : 0;

    float myll = -CUDART_INF_F;
    int   myu  = 0;

    #pragma unroll
    for (int c = 0; c < N_CAND; c++) {
        const int u = __shfl_sync(0xffffffffu, ucached, c);
        const float* H = g_H + (size_t)(pbase + u) * DDIM;
        float p = x0 * H[lane] + ((lane < 28) ? x1 * H[lane + 32] : 0.f);
        #pragma unroll
        for (int o = 16; o; o >>= 1) p += __shfl_xor_sync(0xffffffffu, p, o);
        const float llc = g_LLC[pbase + u] + p;
        if (lane == c) { myll = llc; myu = u; }
    }
    if (lane == 10) myll = noise_lp[0];

    // softmax across lanes 0..10
    float mx = myll;
    #pragma unroll
    for (int o = 16; o; o >>= 1) mx = fmaxf(mx, __shfl_xor_sync(0xffffffffu, mx, o));
    const float ex = (lane < 11) ? __expf(myll - mx) : 0.f;
    float sm = ex;
    #pragma unroll
    for (int o = 16; o; o >>= 1) sm += __shfl_xor_sync(0xffffffffu, sm, o);

    if (lane < N_CAND) {
        const float qv = ex / sm;
        const int pos = atomicAdd(&g_cursor[myu], 1);
        if (pos < CAP) {
            g_sn[myu * CAP + pos] = s;
            g_sq[myu * CAP + pos] = qv;
        }
    }
}

// ---------------------------------------------------------------------------
// Kernel 3: per-unit weighted reduction. One block per unit.
// out[u,0] = sum q ; out[u,1+d] = sum q * xf[d]
// ---------------------------------------------------------------------------
__global__ void __launch_bounds__(256) k_reduce(const float* __restrict__ features,
                                                float* __restrict__ out)
{
    const int u    = blockIdx.x;
    const int t    = threadIdx.x;
    const int warp = t >> 5;
    const int lane = t & 31;

    int cnt = g_cursor[u];
    if (cnt > CAP) cnt = CAP;

    float a0 = 0.f, a1 = 0.f, ac = 0.f;
    for (int e = warp; e < cnt; e += 8) {
        const int   n = g_sn[u * CAP + e];
        const float q = g_sq[u * CAP + e];
        const float* xf = features + (size_t)n * DDIM;
        a0 = fmaf(q, xf[lane], a0);
        if (lane < 28) a1 = fmaf(q, xf[lane + 32], a1);
        ac += q;
    }

    __shared__ float sh[8][OUT_COLS];
    sh[warp][1 + lane] = a0;                 // dims 0..31 -> cols 1..32
    if (lane < 28) sh[warp][33 + lane] = a1; // dims 32..59 -> cols 33..60
    if (lane == 0) sh[warp][0] = ac;         // count column
    __syncthreads();

    if (t < OUT_COLS) {
        float sum = 0.f;
        #pragma unroll
        for (int w2 = 0; w2 < 8; w2++) sum += sh[w2][t];
        out[u * OUT_COLS + t] = sum;
    }
}

// ---------------------------------------------------------------------------
// Input order (metadata): features, mu, Coo_inv, Coo_logdet, log_proportions,
//                         noise_log_prop, cands, nid, obs_ix
// Coo_logdet is unused (cancels in the softmax).
// ---------------------------------------------------------------------------
extern "C" void kernel_launch(void* const* d_in, const int* in_sizes, int n_in,
                              void* d_out, int out_size)
{
    const float* features  = (const float*)d_in[0];
    const float* mu        = (const float*)d_in[1];
    const float* Coo_inv   = (const float*)d_in[2];
    const float* logprop   = (const float*)d_in[4];
    const float* noise_lp  = (const float*)d_in[5];
    const int*   cands     = (const int*)d_in[6];
    const int*   nidp      = (const int*)d_in[7];
    const int*   obs_ix    = (const int*)d_in[8];
    float* out = (float*)d_out;

    k_pre<<<N_NEIGHB, 256>>>(mu, Coo_inv, obs_ix, logprop);
    k_main<<<N_SPIKES / 8, 256>>>(features, cands, nidp, noise_lp);
    k_reduce<<<N_UNITS, 256>>>(features, out);
}

// round 2
// speedup vs baseline: 1.0453x; 1.0453x over previous
#include <cuda_runtime.h>
#include <math_constants.h>

#define N_SPIKES 16384
#define N_UNITS  256
#define N_NEIGHB 128
#define RANK     5
#define NCH      64
#define NCO      12
#define N_CAND   10
#define DDIM     60
#define OUT_COLS 61
#define CAP      2048

// Precomputed tables (device globals; no runtime allocation)
__device__ __align__(16) float g_H[N_NEIGHB * N_UNITS * DDIM];  // H[nid,u,:] = Coo_inv[nid] @ nu(nid,u)
__device__ float g_LLC[N_NEIGHB * N_UNITS];                     // logprop[u] - 0.5 * nu^T C nu
__device__ int   g_cursor[N_UNITS];
__device__ int   g_sn[N_UNITS * CAP];
__device__ float g_sq[N_UNITS * CAP];

// ---------------------------------------------------------------------------
// Kernel 1: per-(nid, unit-quarter) precompute of H and LLC.
// grid = 512: block b -> nid = b>>2, units [(b&3)*64, +64). Each of 8 warps
// handles 8 units. C in shared with pitch 61 (conflict-free: gcd(61,32)=1).
// Block 0 also zeroes the bucket cursors.
// ---------------------------------------------------------------------------
__global__ void __launch_bounds__(256) k_pre(const float* __restrict__ mu,
                                             const float* __restrict__ Cinv,
                                             const int*   __restrict__ obs_ix,
                                             const float* __restrict__ logprop)
{
    __shared__ float Csh[DDIM * 61];
    __shared__ float nub[8][8][64];   // [warp][unit-in-batch][e]
    __shared__ int   obs[NCO];

    const int nidv = blockIdx.x >> 2;
    const int quad = blockIdx.x & 3;
    const int t    = threadIdx.x;
    const int warp = t >> 5;
    const int lane = t & 31;

    if (blockIdx.x == 0) g_cursor[t] = 0;   // blockDim.x == 256 == N_UNITS

    if (t < NCO) obs[t] = obs_ix[nidv * NCO + t];

    const float* C = Cinv + nidv * (DDIM * DDIM);
    for (int i = t; i < DDIM * DDIM; i += 256) {
        int r = i / DDIM, c = i % DDIM;
        Csh[r * 61 + c] = C[i];
    }
    __syncthreads();

    const int d0 = lane;            // always valid (< 60)
    const int d1 = lane + 32;       // valid when lane < 28
    const bool has1 = (d1 < DDIM);
    const int r0 = d0 / NCO, k0 = d0 % NCO;
    const int r1 = has1 ? (d1 / NCO) : 0;
    const int k1 = has1 ? (d1 % NCO) : 0;
    const int o0 = obs[k0];
    const int o1 = obs[k1];

    const int ubase = quad * 64 + warp * 8;

    // gather nu for 8 units into shared
    #pragma unroll
    for (int j = 0; j < 8; j++) {
        const int u = ubase + j;
        nub[warp][j][d0] = mu[u * (RANK * NCH) + r0 * NCH + o0];
        if (has1)
            nub[warp][j][d1] = mu[u * (RANK * NCH) + r1 * NCH + o1];
    }
    __syncwarp();

    float acc0[8], acc1[8];
    #pragma unroll
    for (int j = 0; j < 8; j++) { acc0[j] = 0.f; acc1[j] = 0.f; }

    #pragma unroll 6
    for (int e = 0; e < DDIM; e++) {
        const float c0 = Csh[d0 * 61 + e];
        const float c1 = has1 ? Csh[d1 * 61 + e] : 0.f;
        #pragma unroll
        for (int j = 0; j < 8; j++) {
            const float ne = nub[warp][j][e];
            acc0[j] = fmaf(c0, ne, acc0[j]);
            acc1[j] = fmaf(c1, ne, acc1[j]);
        }
    }

    #pragma unroll
    for (int j = 0; j < 8; j++) {
        const int u = ubase + j;
        float* Hrow = g_H + (size_t)(nidv * N_UNITS + u) * DDIM;
        Hrow[d0] = acc0[j];
        if (has1) Hrow[d1] = acc1[j];
        // G = nu^T C nu = h . nu
        float part = acc0[j] * nub[warp][j][d0]
                   + (has1 ? acc1[j] * nub[warp][j][d1] : 0.f);
        #pragma unroll
        for (int o = 16; o; o >>= 1) part += __shfl_xor_sync(0xffffffffu, part, o);
        if (lane == 0)
            g_LLC[nidv * N_UNITS + u] = logprop[u] - 0.5f * part;
    }
}

// ---------------------------------------------------------------------------
// Kernel 2: per-spike responsibilities. One warp per spike.
// All 20 H loads issued up front (MLP), 10 independent accumulators, single
// batched butterfly reduction (5 stages x 10 regs, ILP instead of serial).
// ---------------------------------------------------------------------------
__global__ void __launch_bounds__(256) k_main(const float* __restrict__ features,
                                              const int*   __restrict__ cands,
                                              const int*   __restrict__ nid,
                                              const float* __restrict__ noise_lp)
{
    const int t    = threadIdx.x;
    const int warp = t >> 5;
    const int lane = t & 31;
    const int s    = blockIdx.x * 8 + warp;

    const float* xf = features + (size_t)s * DDIM;
    const float x0 = xf[lane];
    const float x1 = (lane < 28) ? xf[lane + 32] : 0.f;

    const int nidv  = nid[s];
    const int pbase = nidv * N_UNITS;
    const int ucached = (lane < N_CAND) ? cands[s * N_CAND + lane] : 0;
    const float llc_l = (lane < N_CAND) ? g_LLC[pbase + ucached] : 0.f;

    // issue all 20 H loads before any reduction (high MLP)
    float h0[N_CAND], h1[N_CAND];
    #pragma unroll
    for (int c = 0; c < N_CAND; c++) {
        const int u = __shfl_sync(0xffffffffu, ucached, c);
        const float* H = g_H + (size_t)(pbase + u) * DDIM;
        h0[c] = __ldg(&H[lane]);
        h1[c] = (lane < 28) ? __ldg(&H[lane + 32]) : 0.f;
    }

    float acc[N_CAND];
    #pragma unroll
    for (int c = 0; c < N_CAND; c++)
        acc[c] = fmaf(x0, h0[c], x1 * h1[c]);

    // batched butterfly: 5 stages, 10 independent values per stage
    #pragma unroll
    for (int o = 16; o; o >>= 1) {
        #pragma unroll
        for (int c = 0; c < N_CAND; c++)
            acc[c] += __shfl_xor_sync(0xffffffffu, acc[c], o);
    }

    // lane c takes acc[c] (static-index select chain; no dynamic reg indexing)
    float myp = acc[0];
    #pragma unroll
    for (int c = 1; c < N_CAND; c++)
        if (lane == c) myp = acc[c];

    float myll = -CUDART_INF_F;
    if (lane < N_CAND) myll = llc_l + myp;
    if (lane == N_CAND) myll = noise_lp[0];

    // softmax across lanes 0..10
    float mx = myll;
    #pragma unroll
    for (int o = 16; o; o >>= 1) mx = fmaxf(mx, __shfl_xor_sync(0xffffffffu, mx, o));
    const float ex = (lane <= N_CAND) ? __expf(myll - mx) : 0.f;
    float sm = ex;
    #pragma unroll
    for (int o = 16; o; o >>= 1) sm += __shfl_xor_sync(0xffffffffu, sm, o);

    if (lane < N_CAND) {
        const float qv = ex / sm;
        const int u = ucached;
        const int pos = atomicAdd(&g_cursor[u], 1);
        if (pos < CAP) {
            g_sn[u * CAP + pos] = s;
            g_sq[u * CAP + pos] = qv;
        }
    }
}

// ---------------------------------------------------------------------------
// Kernel 3: per-unit weighted reduction. One block per unit.
// 4-wide manual unroll per warp: 4 independent index->feature load chains.
// ---------------------------------------------------------------------------
__global__ void __launch_bounds__(256) k_reduce(const float* __restrict__ features,
                                                float* __restrict__ out)
{
    const int u    = blockIdx.x;
    const int t    = threadIdx.x;
    const int warp = t >> 5;
    const int lane = t & 31;

    int cnt = g_cursor[u];
    if (cnt > CAP) cnt = CAP;

    const int base = u * CAP;
    float a0 = 0.f, a1 = 0.f, ac = 0.f;

    for (int eb = warp * 4; eb < cnt; eb += 32) {
        // up to 4 independent records per step (uniform broadcast index loads)
        int   n[4];
        float q[4];
        #pragma unroll
        for (int i = 0; i < 4; i++) {
            const bool v = (eb + i) < cnt;
            n[i] = v ? g_sn[base + eb + i] : 0;
            q[i] = v ? g_sq[base + eb + i] : 0.f;
        }
        float f0[4], f1[4];
        #pragma unroll
        for (int i = 0; i < 4; i++) {
            const float* xf = features + (size_t)n[i] * DDIM;
            f0[i] = __ldg(&xf[lane]);
            f1[i] = (lane < 28) ? __ldg(&xf[lane + 32]) : 0.f;
        }
        #pragma unroll
        for (int i = 0; i < 4; i++) {
            a0 = fmaf(q[i], f0[i], a0);
            a1 = fmaf(q[i], f1[i], a1);
            ac += q[i];
        }
    }

    __shared__ float sh[8][OUT_COLS];
    sh[warp][1 + lane] = a0;                 // dims 0..31 -> cols 1..32
    if (lane < 28) sh[warp][33 + lane] = a1; // dims 32..59 -> cols 33..60
    if (lane == 0) sh[warp][0] = ac;         // count column
    __syncthreads();

    if (t < OUT_COLS) {
        float sum = 0.f;
        #pragma unroll
        for (int w2 = 0; w2 < 8; w2++) sum += sh[w2][t];
        out[u * OUT_COLS + t] = sum;
    }
}

// ---------------------------------------------------------------------------
// Input order (metadata): features, mu, Coo_inv, Coo_logdet, log_proportions,
//                         noise_log_prop, cands, nid, obs_ix
// Coo_logdet is unused (cancels in the softmax).
// ---------------------------------------------------------------------------
extern "C" void kernel_launch(void* const* d_in, const int* in_sizes, int n_in,
                              void* d_out, int out_size)
{
    const float* features  = (const float*)d_in[0];
    const float* mu        = (const float*)d_in[1];
    const float* Coo_inv   = (const float*)d_in[2];
    const float* logprop   = (const float*)d_in[4];
    const float* noise_lp  = (const float*)d_in[5];
    const int*   cands     = (const int*)d_in[6];
    const int*   nidp      = (const int*)d_in[7];
    const int*   obs_ix    = (const int*)d_in[8];
    float* out = (float*)d_out;

    k_pre<<<N_NEIGHB * 4, 256>>>(mu, Coo_inv, obs_ix, logprop);
    k_main<<<N_SPIKES / 8, 256>>>(features, cands, nidp, noise_lp);
    k_reduce<<<N_UNITS, 256>>>(features, out);
}

// round 3
// speedup vs baseline: 2.2514x; 2.1538x over previous
#include <cuda_runtime.h>
#include <math_constants.h>

#define N_SPIKES 16384
#define N_UNITS  256
#define N_NEIGHB 128
#define RANK     5
#define NCH      64
#define NCO      12
#define N_CAND   10
#define DDIM     60
#define OUT_COLS 61
#define CAP      2048
#define CPITCH   32          // cursor stride in ints = 128B (avoid L2 atomic line collisions)

// Precomputed tables (device globals; no runtime allocation)
__device__ __align__(16) float g_H[N_NEIGHB * N_UNITS * DDIM];  // H[nid,u,:] = Coo_inv[nid] @ nu(nid,u)
__device__ float g_LLC[N_NEIGHB * N_UNITS];                     // logprop[u] - 0.5 * nu^T C nu
__device__ int   g_cursor[N_UNITS * CPITCH];                    // 128B-strided counters
__device__ __align__(16) int2 g_rec[N_UNITS * CAP];             // packed (spike, bits(q))

// ---------------------------------------------------------------------------
// Kernel 1: per-(nid, unit-quarter) precompute of H and LLC.
// grid = 512: block b -> nid = b>>2, units [(b&3)*64, +64). Each of 8 warps
// handles 8 units. C in shared, pitch 68 floats (float4 conflict-free).
// Vectorized float4 shared reads: 2.5 LDS / e-iter instead of 10.
// Block 0 also zeroes the bucket cursors.
// ---------------------------------------------------------------------------
__global__ void __launch_bounds__(256) k_pre(const float* __restrict__ mu,
                                             const float* __restrict__ Cinv,
                                             const int*   __restrict__ obs_ix,
                                             const float* __restrict__ logprop)
{
    __shared__ __align__(16) float Csh[DDIM * 68];
    __shared__ __align__(16) float nub[8][8][64];   // [warp][unit-in-batch][e]
    __shared__ int   obs[NCO];

    const int nidv = blockIdx.x >> 2;
    const int quad = blockIdx.x & 3;
    const int t    = threadIdx.x;
    const int warp = t >> 5;
    const int lane = t & 31;

    if (blockIdx.x == 0) g_cursor[t * CPITCH] = 0;   // 256 threads zero 256 counters

    if (t < NCO) obs[t] = obs_ix[nidv * NCO + t];

    const float* C = Cinv + nidv * (DDIM * DDIM);
    for (int i = t; i < DDIM * DDIM; i += 256) {
        int r = i / DDIM, c = i % DDIM;
        Csh[r * 68 + c] = C[i];
    }
    __syncthreads();

    const int d0 = lane;            // always valid (< 60)
    const int d1 = lane + 32;       // valid when lane < 28
    const bool has1 = (d1 < DDIM);
    const int r0 = d0 / NCO, k0 = d0 % NCO;
    const int r1 = has1 ? (d1 / NCO) : 0;
    const int k1 = has1 ? (d1 % NCO) : 0;
    const int o0 = obs[k0];
    const int o1 = obs[k1];

    const int ubase = quad * 64 + warp * 8;

    // gather nu for 8 units into shared
    #pragma unroll
    for (int j = 0; j < 8; j++) {
        const int u = ubase + j;
        nub[warp][j][d0] = mu[u * (RANK * NCH) + r0 * NCH + o0];
        if (has1)
            nub[warp][j][d1] = mu[u * (RANK * NCH) + r1 * NCH + o1];
    }
    __syncwarp();

    float acc0[8], acc1[8];
    #pragma unroll
    for (int j = 0; j < 8; j++) { acc0[j] = 0.f; acc1[j] = 0.f; }

    const float4* Crow0 = reinterpret_cast<const float4*>(Csh + d0 * 68);
    const float4* Crow1 = reinterpret_cast<const float4*>(Csh + d1 * 68);

    #pragma unroll 5
    for (int g = 0; g < DDIM / 4; g++) {
        const float4 c0 = Crow0[g];
        const float4 c1 = has1 ? Crow1[g] : make_float4(0.f, 0.f, 0.f, 0.f);
        #pragma unroll
        for (int j = 0; j < 8; j++) {
            const float4 nv = reinterpret_cast<const float4*>(nub[warp][j])[g];
            acc0[j] = fmaf(c0.x, nv.x, acc0[j]);
            acc0[j] = fmaf(c0.y, nv.y, acc0[j]);
            acc0[j] = fmaf(c0.z, nv.z, acc0[j]);
            acc0[j] = fmaf(c0.w, nv.w, acc0[j]);
            acc1[j] = fmaf(c1.x, nv.x, acc1[j]);
            acc1[j] = fmaf(c1.y, nv.y, acc1[j]);
            acc1[j] = fmaf(c1.z, nv.z, acc1[j]);
            acc1[j] = fmaf(c1.w, nv.w, acc1[j]);
        }
    }

    #pragma unroll
    for (int j = 0; j < 8; j++) {
        const int u = ubase + j;
        float* Hrow = g_H + (size_t)(nidv * N_UNITS + u) * DDIM;
        Hrow[d0] = acc0[j];
        if (has1) Hrow[d1] = acc1[j];
        // G = nu^T C nu = h . nu
        float part = acc0[j] * nub[warp][j][d0]
                   + (has1 ? acc1[j] * nub[warp][j][d1] : 0.f);
        #pragma unroll
        for (int o = 16; o; o >>= 1) part += __shfl_xor_sync(0xffffffffu, part, o);
        if (lane == 0)
            g_LLC[nidv * N_UNITS + u] = logprop[u] - 0.5f * part;
    }
}

// ---------------------------------------------------------------------------
// Kernel 2: per-spike responsibilities. One warp per spike.
// All 20 H loads issued up front (MLP), 10 independent accumulators, single
// batched butterfly reduction. Scatter via 128B-strided cursors + packed
// int2 records (one STG.64 per (spike,q)).
// ---------------------------------------------------------------------------
__global__ void __launch_bounds__(256) k_main(const float* __restrict__ features,
                                              const int*   __restrict__ cands,
                                              const int*   __restrict__ nid,
                                              const float* __restrict__ noise_lp)
{
    const int t    = threadIdx.x;
    const int warp = t >> 5;
    const int lane = t & 31;
    const int s    = blockIdx.x * 8 + warp;

    const float* xf = features + (size_t)s * DDIM;
    const float x0 = xf[lane];
    const float x1 = (lane < 28) ? xf[lane + 32] : 0.f;

    const int nidv  = nid[s];
    const int pbase = nidv * N_UNITS;
    const int ucached = (lane < N_CAND) ? cands[s * N_CAND + lane] : 0;
    const float llc_l = (lane < N_CAND) ? g_LLC[pbase + ucached] : 0.f;

    // issue all 20 H loads before any reduction (high MLP)
    float h0[N_CAND], h1[N_CAND];
    #pragma unroll
    for (int c = 0; c < N_CAND; c++) {
        const int u = __shfl_sync(0xffffffffu, ucached, c);
        const float* H = g_H + (size_t)(pbase + u) * DDIM;
        h0[c] = __ldg(&H[lane]);
        h1[c] = (lane < 28) ? __ldg(&H[lane + 32]) : 0.f;
    }

    float acc[N_CAND];
    #pragma unroll
    for (int c = 0; c < N_CAND; c++)
        acc[c] = fmaf(x0, h0[c], x1 * h1[c]);

    // batched butterfly: 5 stages, 10 independent values per stage
    #pragma unroll
    for (int o = 16; o; o >>= 1) {
        #pragma unroll
        for (int c = 0; c < N_CAND; c++)
            acc[c] += __shfl_xor_sync(0xffffffffu, acc[c], o);
    }

    // lane c takes acc[c] (static-index select chain; no dynamic reg indexing)
    float myp = acc[0];
    #pragma unroll
    for (int c = 1; c < N_CAND; c++)
        if (lane == c) myp = acc[c];

    float myll = -CUDART_INF_F;
    if (lane < N_CAND) myll = llc_l + myp;
    if (lane == N_CAND) myll = noise_lp[0];

    // softmax across lanes 0..10
    float mx = myll;
    #pragma unroll
    for (int o = 16; o; o >>= 1) mx = fmaxf(mx, __shfl_xor_sync(0xffffffffu, mx, o));
    const float ex = (lane <= N_CAND) ? __expf(myll - mx) : 0.f;
    float sm = ex;
    #pragma unroll
    for (int o = 16; o; o >>= 1) sm += __shfl_xor_sync(0xffffffffu, sm, o);

    if (lane < N_CAND) {
        const float qv = ex / sm;
        const int u = ucached;
        const int pos = atomicAdd(&g_cursor[u * CPITCH], 1);
        if (pos < CAP) {
            g_rec[u * CAP + pos] = make_int2(s, __float_as_int(qv));
        }
    }
}

// ---------------------------------------------------------------------------
// Kernel 3: per-unit weighted reduction. One block per unit.
// 4-wide manual unroll per warp: 4 independent index->feature load chains.
// ---------------------------------------------------------------------------
__global__ void __launch_bounds__(256) k_reduce(const float* __restrict__ features,
                                                float* __restrict__ out)
{
    const int u    = blockIdx.x;
    const int t    = threadIdx.x;
    const int warp = t >> 5;
    const int lane = t & 31;

    int cnt = g_cursor[u * CPITCH];
    if (cnt > CAP) cnt = CAP;

    const int base = u * CAP;
    float a0 = 0.f, a1 = 0.f, ac = 0.f;

    for (int eb = warp * 4; eb < cnt; eb += 32) {
        // up to 4 independent records per step (uniform broadcast loads)
        int   n[4];
        float q[4];
        #pragma unroll
        for (int i = 0; i < 4; i++) {
            const bool v = (eb + i) < cnt;
            const int2 rec = v ? g_rec[base + eb + i] : make_int2(0, 0);
            n[i] = rec.x;
            q[i] = v ? __int_as_float(rec.y) : 0.f;
        }
        float f0[4], f1[4];
        #pragma unroll
        for (int i = 0; i < 4; i++) {
            const float* xf = features + (size_t)n[i] * DDIM;
            f0[i] = __ldg(&xf[lane]);
            f1[i] = (lane < 28) ? __ldg(&xf[lane + 32]) : 0.f;
        }
        #pragma unroll
        for (int i = 0; i < 4; i++) {
            a0 = fmaf(q[i], f0[i], a0);
            a1 = fmaf(q[i], f1[i], a1);
            ac += q[i];
        }
    }

    __shared__ float sh[8][OUT_COLS];
    sh[warp][1 + lane] = a0;                 // dims 0..31 -> cols 1..32
    if (lane < 28) sh[warp][33 + lane] = a1; // dims 32..59 -> cols 33..60
    if (lane == 0) sh[warp][0] = ac;         // count column
    __syncthreads();

    if (t < OUT_COLS) {
        float sum = 0.f;
        #pragma unroll
        for (int w2 = 0; w2 < 8; w2++) sum += sh[w2][t];
        out[u * OUT_COLS + t] = sum;
    }
}

// ---------------------------------------------------------------------------
// Input order (metadata): features, mu, Coo_inv, Coo_logdet, log_proportions,
//                         noise_log_prop, cands, nid, obs_ix
// Coo_logdet is unused (cancels in the softmax).
// ---------------------------------------------------------------------------
extern "C" void kernel_launch(void* const* d_in, const int* in_sizes, int n_in,
                              void* d_out, int out_size)
{
    const float* features  = (const float*)d_in[0];
    const float* mu        = (const float*)d_in[1];
    const float* Coo_inv   = (const float*)d_in[2];
    const float* logprop   = (const float*)d_in[4];
    const float* noise_lp  = (const float*)d_in[5];
    const int*   cands     = (const int*)d_in[6];
    const int*   nidp      = (const int*)d_in[7];
    const int*   obs_ix    = (const int*)d_in[8];
    float* out = (float*)d_out;

    k_pre<<<N_NEIGHB * 4, 256>>>(mu, Coo_inv, obs_ix, logprop);
    k_main<<<N_SPIKES / 8, 256>>>(features, cands, nidp, noise_lp);
    k_reduce<<<N_UNITS, 256>>>(features, out);
}

// round 4
// speedup vs baseline: 2.3710x; 1.0531x over previous
#include <cuda_runtime.h>
#include <math_constants.h>

#define N_SPIKES 16384
#define N_UNITS  256
#define N_NEIGHB 128
#define RANK     5
#define NCH      64
#define NCO      12
#define N_CAND   10
#define DDIM     60
#define OUT_COLS 61
#define CAP      2048
#define CPITCH   32          // cursor stride in ints = 128B (avoid L2 atomic line collisions)

typedef unsigned long long u64;

// packed fp32x2 FMA (sm_100+): d = a*b + c elementwise on (lo,hi) pairs
#define FMA2(d_, a_, b_, c_) \
    asm("fma.rn.f32x2 %0, %1, %2, %3;" : "=l"(d_) : "l"(a_), "l"(b_), "l"(c_))

// Precomputed tables (device globals; no runtime allocation)
__device__ __align__(16) float g_H[N_NEIGHB * N_UNITS * DDIM];  // H[nid,u,:] = Coo_inv[nid] @ nu(nid,u)
__device__ float g_LLC[N_NEIGHB * N_UNITS];                     // logprop[u] - 0.5 * nu^T C nu
__device__ int   g_cursor[N_UNITS * CPITCH];                    // 128B-strided counters
__device__ __align__(16) int2 g_rec[N_UNITS * CAP];             // packed (spike, bits(q))

// ---------------------------------------------------------------------------
// Kernel 1: per-(nid, unit-octant) precompute of H and LLC.
// grid = 1024: block b -> nid = b>>3, units [(b&7)*32, +32). 8 warps x 4 units.
// C in shared, pitch 68 floats (16B-aligned rows). Inner product uses packed
// fma.rn.f32x2 over e-pairs: FMA issue count halved vs scalar.
// Block 0 also zeroes the bucket cursors.
// ---------------------------------------------------------------------------
__global__ void __launch_bounds__(256) k_pre(const float* __restrict__ mu,
                                             const float* __restrict__ Cinv,
                                             const int*   __restrict__ obs_ix,
                                             const float* __restrict__ logprop)
{
    __shared__ __align__(16) float Csh[DDIM * 68];
    __shared__ __align__(16) float nub[8][4][64];   // [warp][unit-in-batch][e]
    __shared__ int   obs[NCO];

    const int nidv = blockIdx.x >> 3;
    const int oct  = blockIdx.x & 7;
    const int t    = threadIdx.x;
    const int warp = t >> 5;
    const int lane = t & 31;

    if (blockIdx.x == 0) g_cursor[t * CPITCH] = 0;   // 256 threads zero 256 counters

    if (t < NCO) obs[t] = obs_ix[nidv * NCO + t];

    const float* C = Cinv + nidv * (DDIM * DDIM);
    for (int i = t; i < DDIM * DDIM; i += 256) {
        int r = i / DDIM, c = i % DDIM;
        Csh[r * 68 + c] = C[i];
    }
    __syncthreads();

    const int d0 = lane;            // always valid (< 60)
    const int d1 = lane + 32;       // valid when lane < 28
    const bool has1 = (d1 < DDIM);
    const int r0 = d0 / NCO, k0 = d0 % NCO;
    const int r1 = has1 ? (d1 / NCO) : 0;
    const int k1 = has1 ? (d1 % NCO) : 0;
    const int o0 = obs[k0];
    const int o1 = obs[k1];

    const int ubase = oct * 32 + warp * 4;

    // gather nu for 4 units into shared
    #pragma unroll
    for (int j = 0; j < 4; j++) {
        const int u = ubase + j;
        nub[warp][j][d0] = mu[u * (RANK * NCH) + r0 * NCH + o0];
        if (has1)
            nub[warp][j][d1] = mu[u * (RANK * NCH) + r1 * NCH + o1];
    }
    __syncwarp();

    u64 acc0[4], acc1[4];
    #pragma unroll
    for (int j = 0; j < 4; j++) { acc0[j] = 0ull; acc1[j] = 0ull; }

    const double2* Crow0 = reinterpret_cast<const double2*>(Csh + d0 * 68);
    const double2* Crow1 = reinterpret_cast<const double2*>(Csh + d1 * 68);

    #pragma unroll 5
    for (int g = 0; g < DDIM / 4; g++) {
        const double2 c0d = Crow0[g];
        const u64 c0a = __double_as_longlong(c0d.x);
        const u64 c0b = __double_as_longlong(c0d.y);
        u64 c1a = 0ull, c1b = 0ull;
        if (has1) {
            const double2 c1d = Crow1[g];
            c1a = __double_as_longlong(c1d.x);
            c1b = __double_as_longlong(c1d.y);
        }
        #pragma unroll
        for (int j = 0; j < 4; j++) {
            const double2 nvd = reinterpret_cast<const double2*>(nub[warp][j])[g];
            const u64 na = __double_as_longlong(nvd.x);
            const u64 nb = __double_as_longlong(nvd.y);
            FMA2(acc0[j], c0a, na, acc0[j]);
            FMA2(acc0[j], c0b, nb, acc0[j]);
            FMA2(acc1[j], c1a, na, acc1[j]);
            FMA2(acc1[j], c1b, nb, acc1[j]);
        }
    }

    #pragma unroll
    for (int j = 0; j < 4; j++) {
        const int u = ubase + j;
        const float h0 = __int_as_float((int)(acc0[j] & 0xffffffffull))
                       + __int_as_float((int)(acc0[j] >> 32));
        const float h1 = __int_as_float((int)(acc1[j] & 0xffffffffull))
                       + __int_as_float((int)(acc1[j] >> 32));
        float* Hrow = g_H + (size_t)(nidv * N_UNITS + u) * DDIM;
        Hrow[d0] = h0;
        if (has1) Hrow[d1] = h1;
        // G = nu^T C nu = h . nu
        float part = h0 * nub[warp][j][d0]
                   + (has1 ? h1 * nub[warp][j][d1] : 0.f);
        #pragma unroll
        for (int o = 16; o; o >>= 1) part += __shfl_xor_sync(0xffffffffu, part, o);
        if (lane == 0)
            g_LLC[nidv * N_UNITS + u] = logprop[u] - 0.5f * part;
    }
}

// ---------------------------------------------------------------------------
// Kernel 2: per-spike responsibilities. One warp per spike.
// All 20 H loads issued up front (MLP), 10 independent accumulators, single
// batched butterfly reduction. Scatter via 128B-strided cursors + packed
// int2 records (one STG.64 per (spike,q)).
// ---------------------------------------------------------------------------
__global__ void __launch_bounds__(256) k_main(const float* __restrict__ features,
                                              const int*   __restrict__ cands,
                                              const int*   __restrict__ nid,
                                              const float* __restrict__ noise_lp)
{
    const int t    = threadIdx.x;
    const int warp = t >> 5;
    const int lane = t & 31;
    const int s    = blockIdx.x * 8 + warp;

    const float nlp = __ldg(noise_lp);
    const float* xf = features + (size_t)s * DDIM;
    const float x0 = xf[lane];
    const float x1 = (lane < 28) ? xf[lane + 32] : 0.f;

    const int nidv  = __ldg(&nid[s]);
    const int pbase = nidv * N_UNITS;
    const int ucached = (lane < N_CAND) ? __ldg(&cands[s * N_CAND + lane]) : 0;
    const float llc_l = (lane < N_CAND) ? g_LLC[pbase + ucached] : 0.f;

    // issue all 20 H loads before any reduction (high MLP)
    float h0[N_CAND], h1[N_CAND];
    #pragma unroll
    for (int c = 0; c < N_CAND; c++) {
        const int u = __shfl_sync(0xffffffffu, ucached, c);
        const float* H = g_H + (size_t)(pbase + u) * DDIM;
        h0[c] = __ldg(&H[lane]);
        h1[c] = (lane < 28) ? __ldg(&H[lane + 32]) : 0.f;
    }

    float acc[N_CAND];
    #pragma unroll
    for (int c = 0; c < N_CAND; c++)
        acc[c] = fmaf(x0, h0[c], x1 * h1[c]);

    // batched butterfly: 5 stages, 10 independent values per stage
    #pragma unroll
    for (int o = 16; o; o >>= 1) {
        #pragma unroll
        for (int c = 0; c < N_CAND; c++)
            acc[c] += __shfl_xor_sync(0xffffffffu, acc[c], o);
    }

    // lane c takes acc[c] (static-index select chain; no dynamic reg indexing)
    float myp = acc[0];
    #pragma unroll
    for (int c = 1; c < N_CAND; c++)
        if (lane == c) myp = acc[c];

    float myll = -CUDART_INF_F;
    if (lane < N_CAND) myll = llc_l + myp;
    if (lane == N_CAND) myll = nlp;

    // softmax across lanes 0..10
    float mx = myll;
    #pragma unroll
    for (int o = 16; o; o >>= 1) mx = fmaxf(mx, __shfl_xor_sync(0xffffffffu, mx, o));
    const float ex = (lane <= N_CAND) ? __expf(myll - mx) : 0.f;
    float sm = ex;
    #pragma unroll
    for (int o = 16; o; o >>= 1) sm += __shfl_xor_sync(0xffffffffu, sm, o);

    if (lane < N_CAND) {
        const float qv = ex / sm;
        const int u = ucached;
        const int pos = atomicAdd(&g_cursor[u * CPITCH], 1);
        if (pos < CAP) {
            g_rec[u * CAP + pos] = make_int2(s, __float_as_int(qv));
        }
    }
}

// ---------------------------------------------------------------------------
// Kernel 3: per-unit weighted reduction. One block per unit.
// 8-wide manual unroll per warp: 8 independent index->feature load chains.
// ---------------------------------------------------------------------------
__global__ void __launch_bounds__(256) k_reduce(const float* __restrict__ features,
                                                float* __restrict__ out)
{
    const int u    = blockIdx.x;
    const int t    = threadIdx.x;
    const int warp = t >> 5;
    const int lane = t & 31;

    int cnt = g_cursor[u * CPITCH];
    if (cnt > CAP) cnt = CAP;

    const int base = u * CAP;
    float a0 = 0.f, a1 = 0.f, ac = 0.f;

    for (int eb = warp * 8; eb < cnt; eb += 64) {
        // up to 8 independent records per step (uniform broadcast loads)
        int   n[8];
        float q[8];
        #pragma unroll
        for (int i = 0; i < 8; i++) {
            const bool v = (eb + i) < cnt;
            const int2 rec = v ? g_rec[base + eb + i] : make_int2(0, 0);
            n[i] = rec.x;
            q[i] = v ? __int_as_float(rec.y) : 0.f;
        }
        float f0[8], f1[8];
        #pragma unroll
        for (int i = 0; i < 8; i++) {
            const float* xf = features + (size_t)n[i] * DDIM;
            f0[i] = __ldg(&xf[lane]);
            f1[i] = (lane < 28) ? __ldg(&xf[lane + 32]) : 0.f;
        }
        #pragma unroll
        for (int i = 0; i < 8; i++) {
            a0 = fmaf(q[i], f0[i], a0);
            a1 = fmaf(q[i], f1[i], a1);
            ac += q[i];
        }
    }

    __shared__ float sh[8][OUT_COLS];
    sh[warp][1 + lane] = a0;                 // dims 0..31 -> cols 1..32
    if (lane < 28) sh[warp][33 + lane] = a1; // dims 32..59 -> cols 33..60
    if (lane == 0) sh[warp][0] = ac;         // count column
    __syncthreads();

    if (t < OUT_COLS) {
        float sum = 0.f;
        #pragma unroll
        for (int w2 = 0; w2 < 8; w2++) sum += sh[w2][t];
        out[u * OUT_COLS + t] = sum;
    }
}

// ---------------------------------------------------------------------------
// Input order (metadata): features, mu, Coo_inv, Coo_logdet, log_proportions,
//                         noise_log_prop, cands, nid, obs_ix
// Coo_logdet is unused (cancels in the softmax).
// ---------------------------------------------------------------------------
extern "C" void kernel_launch(void* const* d_in, const int* in_sizes, int n_in,
                              void* d_out, int out_size)
{
    const float* features  = (const float*)d_in[0];
    const float* mu        = (const float*)d_in[1];
    const float* Coo_inv   = (const float*)d_in[2];
    const float* logprop   = (const float*)d_in[4];
    const float* noise_lp  = (const float*)d_in[5];
    const int*   cands     = (const int*)d_in[6];
    const int*   nidp      = (const int*)d_in[7];
    const int*   obs_ix    = (const int*)d_in[8];
    float* out = (float*)d_out;

    k_pre<<<N_NEIGHB * 8, 256>>>(mu, Coo_inv, obs_ix, logprop);
    k_main<<<N_SPIKES / 8, 256>>>(features, cands, nidp, noise_lp);
    k_reduce<<<N_UNITS, 256>>>(features, out);
}

// round 5
// speedup vs baseline: 2.5086x; 1.0580x over previous
#include <cuda_runtime.h>
#include <math_constants.h>

#define N_SPIKES 16384
#define N_UNITS  256
#define N_NEIGHB 128
#define RANK     5
#define NCH      64
#define NCO      12
#define N_CAND   10
#define DDIM     60
#define OUT_COLS 61
#define CAP      2048
#define CPITCH   32          // cursor stride in ints = 128B (avoid L2 atomic line collisions)
#define CSH_PITCH 66         // words; lane l u64 load hits banks (2l,2l+1): conflict-free

typedef unsigned long long u64;

// packed fp32x2 FMA (sm_100+): d = a*b + c elementwise on (lo,hi) pairs
#define FMA2(d_, a_, b_, c_) \
    asm("fma.rn.f32x2 %0, %1, %2, %3;" : "=l"(d_) : "l"(a_), "l"(b_), "l"(c_))

// Precomputed tables (device globals; no runtime allocation)
__device__ __align__(16) float g_H[N_NEIGHB * N_UNITS * DDIM];  // H[nid,u,:] = Coo_inv[nid] @ nu(nid,u)
__device__ float g_LLC[N_NEIGHB * N_UNITS];                     // logprop[u] - 0.5 * nu^T C nu
__device__ int   g_cursor[N_UNITS * CPITCH];                    // 128B-strided counters
__device__ __align__(16) int2 g_rec[N_UNITS * CAP];             // packed (spike, bits(q))

// ---------------------------------------------------------------------------
// Kernel 1: per-(nid, unit-quarter) precompute of H and LLC.
// grid = 512: block b -> nid = b>>2, units [(b&3)*64, +64). 8 warps x 8 units.
// C in shared, pitch 66 words (conflict-free LDS.64). Inner product uses
// packed fma.rn.f32x2 over e-pairs, ordered j-inner for 8-way ILP.
// Block 0 also zeroes the bucket cursors.
// ---------------------------------------------------------------------------
__global__ void __launch_bounds__(256) k_pre(const float* __restrict__ mu,
                                             const float* __restrict__ Cinv,
                                             const int*   __restrict__ obs_ix,
                                             const float* __restrict__ logprop)
{
    __shared__ __align__(16) float Csh[DDIM * CSH_PITCH];
    __shared__ __align__(16) float nub[8][8][64];   // [warp][unit-in-batch][e]
    __shared__ int   obs[NCO];

    const int nidv = blockIdx.x >> 2;
    const int quad = blockIdx.x & 3;
    const int t    = threadIdx.x;
    const int warp = t >> 5;
    const int lane = t & 31;

    if (blockIdx.x == 0) g_cursor[t * CPITCH] = 0;   // 256 threads zero 256 counters

    if (t < NCO) obs[t] = obs_ix[nidv * NCO + t];

    // C fill with u64 copies: each row is exactly 30 u64, no row crossing.
    {
        const u64* C2 = reinterpret_cast<const u64*>(Cinv + (size_t)nidv * (DDIM * DDIM));
        for (int f = t; f < DDIM * (DDIM / 2); f += 256) {
            const int r = f / 30, c2 = f % 30;
            reinterpret_cast<u64*>(Csh + r * CSH_PITCH)[c2] = C2[f];
        }
    }
    __syncthreads();

    const int d0 = lane;            // always valid (< 60)
    const int d1 = lane + 32;       // valid when lane < 28
    const bool has1 = (d1 < DDIM);
    const int r0 = d0 / NCO, k0 = d0 % NCO;
    const int r1 = has1 ? (d1 / NCO) : 0;
    const int k1 = has1 ? (d1 % NCO) : 0;
    const int o0 = obs[k0];
    const int o1 = obs[k1];

    const int ubase = quad * 64 + warp * 8;

    // gather nu for 8 units into shared
    #pragma unroll
    for (int j = 0; j < 8; j++) {
        const int u = ubase + j;
        nub[warp][j][d0] = mu[u * (RANK * NCH) + r0 * NCH + o0];
        if (has1)
            nub[warp][j][d1] = mu[u * (RANK * NCH) + r1 * NCH + o1];
    }
    __syncwarp();

    u64 acc0[8], acc1[8];
    #pragma unroll
    for (int j = 0; j < 8; j++) { acc0[j] = 0ull; acc1[j] = 0ull; }

    const u64* Crow0 = reinterpret_cast<const u64*>(Csh + d0 * CSH_PITCH);
    const u64* Crow1 = reinterpret_cast<const u64*>(Csh + d1 * CSH_PITCH);

    #pragma unroll 6
    for (int g = 0; g < DDIM / 2; g++) {       // one e-pair per iteration
        const u64 c0 = Crow0[g];
        const u64 c1 = has1 ? Crow1[g] : 0ull;
        u64 n[8];
        #pragma unroll
        for (int j = 0; j < 8; j++)
            n[j] = reinterpret_cast<const u64*>(nub[warp][j])[g];
        #pragma unroll
        for (int j = 0; j < 8; j++)
            FMA2(acc0[j], c0, n[j], acc0[j]);   // 8 independent chains
        #pragma unroll
        for (int j = 0; j < 8; j++)
            FMA2(acc1[j], c1, n[j], acc1[j]);   // 8 independent chains
    }

    #pragma unroll
    for (int j = 0; j < 8; j++) {
        const int u = ubase + j;
        const float h0 = __int_as_float((int)(acc0[j] & 0xffffffffull))
                       + __int_as_float((int)(acc0[j] >> 32));
        const float h1 = __int_as_float((int)(acc1[j] & 0xffffffffull))
                       + __int_as_float((int)(acc1[j] >> 32));
        float* Hrow = g_H + (size_t)(nidv * N_UNITS + u) * DDIM;
        Hrow[d0] = h0;
        if (has1) Hrow[d1] = h1;
        // G = nu^T C nu = h . nu
        float part = h0 * nub[warp][j][d0]
                   + (has1 ? h1 * nub[warp][j][d1] : 0.f);
        #pragma unroll
        for (int o = 16; o; o >>= 1) part += __shfl_xor_sync(0xffffffffu, part, o);
        if (lane == 0)
            g_LLC[nidv * N_UNITS + u] = logprop[u] - 0.5f * part;
    }
}

// ---------------------------------------------------------------------------
// Kernel 2: per-spike responsibilities. One warp per spike.
// All 20 H loads issued up front (MLP), 10 independent accumulators, single
// batched butterfly reduction. Scatter via 128B-strided cursors + packed
// int2 records (one STG.64 per (spike,q)).
// ---------------------------------------------------------------------------
__global__ void __launch_bounds__(256) k_main(const float* __restrict__ features,
                                              const int*   __restrict__ cands,
                                              const int*   __restrict__ nid,
                                              const float* __restrict__ noise_lp)
{
    const int t    = threadIdx.x;
    const int warp = t >> 5;
    const int lane = t & 31;
    const int s    = blockIdx.x * 8 + warp;

    const float nlp = __ldg(noise_lp);
    const float* xf = features + (size_t)s * DDIM;
    const float x0 = xf[lane];
    const float x1 = (lane < 28) ? xf[lane + 32] : 0.f;

    const int nidv  = __ldg(&nid[s]);
    const int pbase = nidv * N_UNITS;
    const int ucached = (lane < N_CAND) ? __ldg(&cands[s * N_CAND + lane]) : 0;
    const float llc_l = (lane < N_CAND) ? g_LLC[pbase + ucached] : 0.f;

    // issue all 20 H loads before any reduction (high MLP)
    float h0[N_CAND], h1[N_CAND];
    #pragma unroll
    for (int c = 0; c < N_CAND; c++) {
        const int u = __shfl_sync(0xffffffffu, ucached, c);
        const float* H = g_H + (size_t)(pbase + u) * DDIM;
        h0[c] = __ldg(&H[lane]);
        h1[c] = (lane < 28) ? __ldg(&H[lane + 32]) : 0.f;
    }

    float acc[N_CAND];
    #pragma unroll
    for (int c = 0; c < N_CAND; c++)
        acc[c] = fmaf(x0, h0[c], x1 * h1[c]);

    // batched butterfly: 5 stages, 10 independent values per stage
    #pragma unroll
    for (int o = 16; o; o >>= 1) {
        #pragma unroll
        for (int c = 0; c < N_CAND; c++)
            acc[c] += __shfl_xor_sync(0xffffffffu, acc[c], o);
    }

    // lane c takes acc[c] (static-index select chain; no dynamic reg indexing)
    float myp = acc[0];
    #pragma unroll
    for (int c = 1; c < N_CAND; c++)
        if (lane == c) myp = acc[c];

    float myll = -CUDART_INF_F;
    if (lane < N_CAND) myll = llc_l + myp;
    if (lane == N_CAND) myll = nlp;

    // softmax across lanes 0..10
    float mx = myll;
    #pragma unroll
    for (int o = 16; o; o >>= 1) mx = fmaxf(mx, __shfl_xor_sync(0xffffffffu, mx, o));
    const float ex = (lane <= N_CAND) ? __expf(myll - mx) : 0.f;
    float sm = ex;
    #pragma unroll
    for (int o = 16; o; o >>= 1) sm += __shfl_xor_sync(0xffffffffu, sm, o);

    if (lane < N_CAND) {
        const float qv = ex / sm;
        const int u = ucached;
        const int pos = atomicAdd(&g_cursor[u * CPITCH], 1);
        if (pos < CAP) {
            g_rec[u * CAP + pos] = make_int2(s, __float_as_int(qv));
        }
    }
}

// ---------------------------------------------------------------------------
// Kernel 3: per-unit weighted reduction. One block per unit.
// 8-wide manual unroll per warp: 8 independent index->feature load chains.
// ---------------------------------------------------------------------------
__global__ void __launch_bounds__(256) k_reduce(const float* __restrict__ features,
                                                float* __restrict__ out)
{
    const int u    = blockIdx.x;
    const int t    = threadIdx.x;
    const int warp = t >> 5;
    const int lane = t & 31;

    int cnt = g_cursor[u * CPITCH];
    if (cnt > CAP) cnt = CAP;

    const int base = u * CAP;
    float a0 = 0.f, a1 = 0.f, ac = 0.f;

    for (int eb = warp * 8; eb < cnt; eb += 64) {
        // up to 8 independent records per step (uniform broadcast loads)
        int   n[8];
        float q[8];
        #pragma unroll
        for (int i = 0; i < 8; i++) {
            const bool v = (eb + i) < cnt;
            const int2 rec = v ? g_rec[base + eb + i] : make_int2(0, 0);
            n[i] = rec.x;
            q[i] = v ? __int_as_float(rec.y) : 0.f;
        }
        float f0[8], f1[8];
        #pragma unroll
        for (int i = 0; i < 8; i++) {
            const float* xf = features + (size_t)n[i] * DDIM;
            f0[i] = __ldg(&xf[lane]);
            f1[i] = (lane < 28) ? __ldg(&xf[lane + 32]) : 0.f;
        }
        #pragma unroll
        for (int i = 0; i < 8; i++) {
            a0 = fmaf(q[i], f0[i], a0);
            a1 = fmaf(q[i], f1[i], a1);
            ac += q[i];
        }
    }

    __shared__ float sh[8][OUT_COLS];
    sh[warp][1 + lane] = a0;                 // dims 0..31 -> cols 1..32
    if (lane < 28) sh[warp][33 + lane] = a1; // dims 32..59 -> cols 33..60
    if (lane == 0) sh[warp][0] = ac;         // count column
    __syncthreads();

    if (t < OUT_COLS) {
        float sum = 0.f;
        #pragma unroll
        for (int w2 = 0; w2 < 8; w2++) sum += sh[w2][t];
        out[u * OUT_COLS + t] = sum;
    }
}

// ---------------------------------------------------------------------------
// Input order (metadata): features, mu, Coo_inv, Coo_logdet, log_proportions,
//                         noise_log_prop, cands, nid, obs_ix
// Coo_logdet is unused (cancels in the softmax).
// ---------------------------------------------------------------------------
extern "C" void kernel_launch(void* const* d_in, const int* in_sizes, int n_in,
                              void* d_out, int out_size)
{
    const float* features  = (const float*)d_in[0];
    const float* mu        = (const float*)d_in[1];
    const float* Coo_inv   = (const float*)d_in[2];
    const float* logprop   = (const float*)d_in[4];
    const float* noise_lp  = (const float*)d_in[5];
    const int*   cands     = (const int*)d_in[6];
    const int*   nidp      = (const int*)d_in[7];
    const int*   obs_ix    = (const int*)d_in[8];
    float* out = (float*)d_out;

    k_pre<<<N_NEIGHB * 4, 256>>>(mu, Coo_inv, obs_ix, logprop);
    k_main<<<N_SPIKES / 8, 256>>>(features, cands, nidp, noise_lp);
    k_reduce<<<N_UNITS, 256>>>(features, out);
}